// round 9
// baseline (speedup 1.0000x reference)
#include <cuda_runtime.h>

// ---------------- problem constants ----------------
#define NB      4096
#define NNOTES  48
#define NF      256
#define NU      256
#define NG      1024      // 4 * NU (i,f,g,o)
#define K0TOT   516       // padded ih0 (260, last row zero) + hh0 (256)
#define K1TOT   512       // ih1 (256) + hh1 (256)
#define KC      4         // K rows per pipeline chunk
#define NSTAGE  3
#define MROWS   32        // batch rows per CTA
#define NTHR    1024
#define ASTR    36        // transposed-A row stride (32 rows + 4 pad, mult of 4)

typedef unsigned long long u64;

// ---------------- device scratch (static, allocation-guard-safe) ----------------
__device__ __align__(16) float g_W0[K0TOT * NG];   // [k][gatecol] layer 0 (ih pad ++ hh)
__device__ __align__(16) float g_W1[K1TOT * NG];   // [k][gatecol] layer 1 (ih ++ hh)
__device__ __align__(16) float g_b0[NG];
__device__ __align__(16) float g_b1[NG];

// ---------------- helpers ----------------
__device__ __forceinline__ u64 pack2(float x) {
    u64 r;
    asm("mov.b64 %0, {%1, %1};" : "=l"(r) : "r"(__float_as_uint(x)));
    return r;
}
__device__ __forceinline__ u64 pack2f(float lo, float hi) {
    u64 r;
    asm("mov.b64 %0, {%1, %2};" : "=l"(r) : "r"(__float_as_uint(lo)), "r"(__float_as_uint(hi)));
    return r;
}
__device__ __forceinline__ void fma2(u64& acc, u64 a, u64 b) {
    asm("fma.rn.f32x2 %0, %1, %2, %0;" : "+l"(acc) : "l"(a), "l"(b));
}
__device__ __forceinline__ void unpack2(u64 v, float& lo, float& hi) {
    unsigned int a, b;
    asm("mov.b64 {%0, %1}, %2;" : "=r"(a), "=r"(b) : "l"(v));
    lo = __uint_as_float(a);
    hi = __uint_as_float(b);
}
__device__ __forceinline__ float sigf(float x) {
    return 1.0f / (1.0f + expf(-x));
}
__device__ __forceinline__ void cp16(unsigned dst, const float* src) {
    asm volatile("cp.async.ca.shared.global [%0], [%1], 16;" :: "r"(dst), "l"(src) : "memory");
}
__device__ __forceinline__ void cp_commit() {
    asm volatile("cp.async.commit_group;" ::: "memory");
}
__device__ __forceinline__ void cp_wait1() {
    asm volatile("cp.async.wait_group 1;" ::: "memory");
}

// ---------------- prep: transpose + concatenate weights, combine biases ----------------
__global__ void prep_kernel(const float* __restrict__ W_ih0, const float* __restrict__ W_hh0,
                            const float* __restrict__ b_ih0, const float* __restrict__ b_hh0,
                            const float* __restrict__ W_ih1, const float* __restrict__ W_hh1,
                            const float* __restrict__ b_ih1, const float* __restrict__ b_hh1) {
    int tid = blockIdx.x * blockDim.x + threadIdx.x;
    int stride = gridDim.x * blockDim.x;
    for (int i = tid; i < K0TOT * NG; i += stride) {
        int k = i / NG, j = i - k * NG;
        float v;
        if (k < 259)      v = W_ih0[j * 259 + k];     // original IN0 = 259
        else if (k == 259) v = 0.f;                   // pad row (x[259] = 0 too)
        else              v = W_hh0[j * 256 + (k - 260)];
        g_W0[i] = v;
    }
    for (int i = tid; i < K1TOT * NG; i += stride) {
        int k = i / NG, j = i - k * NG;
        g_W1[i] = (k < 256) ? W_ih1[j * 256 + k] : W_hh1[j * 256 + (k - 256)];
    }
    for (int i = tid; i < NG; i += stride) {
        g_b0[i] = b_ih0[i] + b_hh0[i];
        g_b1[i] = b_ih1[i] + b_hh1[i];
    }
}

// ---------------- GEMM over one layer (concatenated ih++hh K range) ----------------
// Thread (rg, ug): rows rg*8..rg*8+7 (lanes = row pairs), unit ug, all 4 gates.
// A operands are TRANSPOSED in smem: A[k][row], row stride ASTR.
// W staged via 3-stage cp.async pipeline, KC k-rows per chunk.
__device__ __forceinline__ void gemm_layer(
    u64 (&acc)[4][4],
    const float* A0, const float* A1, int swChunk,   // A source switches at chunk swChunk
    const float* __restrict__ Wg, int nchunks,
    const float* sh_w, unsigned sw_u32, int tid, int rg8, int ug)
{
    // prologue: stage chunks 0 and 1
#pragma unroll
    for (int p = 0; p < 2; p++) {
        cp16(sw_u32 + (unsigned)(p * (KC * NG) + tid * 4) * 4u, Wg + p * (KC * NG) + tid * 4);
        cp_commit();
    }
    int stage = 0, stage2 = 2;   // stage of chunk ci, and of chunk ci+2
    for (int ci = 0; ci < nchunks; ci++) {
        cp_wait1();              // chunk ci (and older) arrived for THIS thread's copies
        __syncthreads();         // all threads' copies of chunk ci visible; stage2 free
        if (ci + 2 < nchunks) {
            cp16(sw_u32 + (unsigned)(stage2 * (KC * NG) + tid * 4) * 4u,
                 Wg + (size_t)(ci + 2) * (KC * NG) + tid * 4);
        }
        cp_commit();             // always commit (empty groups keep the count consistent)

        const float* wb = sh_w + stage * (KC * NG) + ug;
        const float* ab = (ci < swChunk ? A0 + ci * (KC * ASTR)
                                        : A1 + (ci - swChunk) * (KC * ASTR)) + rg8;
#pragma unroll
        for (int kk = 0; kk < KC; kk++) {
            float4 a03 = *(const float4*)(ab + kk * ASTR);       // rows rg8..rg8+3 (broadcast)
            float4 a47 = *(const float4*)(ab + kk * ASTR + 4);   // rows rg8+4..rg8+7
            u64 ap0 = pack2f(a03.x, a03.y);
            u64 ap1 = pack2f(a03.z, a03.w);
            u64 ap2 = pack2f(a47.x, a47.y);
            u64 ap3 = pack2f(a47.z, a47.w);
            const float* wr = wb + kk * NG;
            u64 wi = pack2(wr[0]);
            u64 wf = pack2(wr[256]);
            u64 wg = pack2(wr[512]);
            u64 wo = pack2(wr[768]);
            fma2(acc[0][0], ap0, wi); fma2(acc[1][0], ap1, wi);
            fma2(acc[2][0], ap2, wi); fma2(acc[3][0], ap3, wi);
            fma2(acc[0][1], ap0, wf); fma2(acc[1][1], ap1, wf);
            fma2(acc[2][1], ap2, wf); fma2(acc[3][1], ap3, wf);
            fma2(acc[0][2], ap0, wg); fma2(acc[1][2], ap1, wg);
            fma2(acc[2][2], ap2, wg); fma2(acc[3][2], ap3, wg);
            fma2(acc[0][3], ap0, wo); fma2(acc[1][3], ap1, wo);
            fma2(acc[2][3], ap2, wo); fma2(acc[3][3], ap3, wo);
        }
        stage = stage + 1;  if (stage == NSTAGE)  stage = 0;
        stage2 = stage2 + 1; if (stage2 == NSTAGE) stage2 = 0;
    }
}

// ---------------- LSTM cell elementwise ----------------
// Thread owns rows rg8..rg8+7 (as 4 lane-pairs) and unit ug; c is thread-exclusive.
// Writes new h into TRANSPOSED layout hT[unit][row].
__device__ __forceinline__ void cell_update(
    u64 (&acc)[4][4], float* c_state, float* hT, int rg8, int ug)
{
    float hn[8];
#pragma unroll
    for (int rp = 0; rp < 4; rp++) {
        float i0, i1, f0, f1, g0, g1, o0, o1;
        unpack2(acc[rp][0], i0, i1);
        unpack2(acc[rp][1], f0, f1);
        unpack2(acc[rp][2], g0, g1);
        unpack2(acc[rp][3], o0, o1);
        int r0 = rg8 + 2 * rp;
        float c0 = c_state[r0 * NU + ug];
        float c1 = c_state[(r0 + 1) * NU + ug];
        float cn0 = sigf(f0) * c0 + sigf(i0) * tanhf(g0);
        float cn1 = sigf(f1) * c1 + sigf(i1) * tanhf(g1);
        c_state[r0 * NU + ug]       = cn0;
        c_state[(r0 + 1) * NU + ug] = cn1;
        hn[2 * rp]     = sigf(o0) * tanhf(cn0);
        hn[2 * rp + 1] = sigf(o1) * tanhf(cn1);
    }
    __syncthreads();   // all GEMM readers of old hT are done
    float4* d = (float4*)(hT + ug * ASTR + rg8);
    d[0] = make_float4(hn[0], hn[1], hn[2], hn[3]);
    d[1] = make_float4(hn[4], hn[5], hn[6], hn[7]);
    __syncthreads();   // new hT visible (output head / next GEMM)
}

// ---------------- main persistent kernel ----------------
__global__ void __launch_bounds__(NTHR, 1)
noteaxis_kernel(const float* __restrict__ feats,
                const float* __restrict__ cond,
                const float* __restrict__ Wout,
                const float* __restrict__ bout,
                float* __restrict__ out)
{
    extern __shared__ float smem[];
    float* sh_w   = smem;                          // 3*4*1024 = 12288 floats
    float* sh_xT  = sh_w + NSTAGE * KC * NG;       // 260*36   = 9360
    float* sh_h0T = sh_xT + 260 * ASTR;            // 256*36   = 9216
    float* sh_h1T = sh_h0T + NU * ASTR;            // 9216
    float* sh_c0  = sh_h1T + NU * ASTR;            // 32*256   = 8192
    float* sh_c1  = sh_c0 + MROWS * NU;            // 8192
    unsigned sw_u32 = (unsigned)__cvta_generic_to_shared(sh_w);

    int tid = threadIdx.x;
    int rg  = tid >> 8;        // 0..3, warp-uniform
    int ug  = tid & 255;       // unit index
    int rg8 = rg * 8;
    size_t batch0 = (size_t)blockIdx.x * MROWS;

    for (int i = tid; i < NU * ASTR; i += NTHR) { sh_h0T[i] = 0.f; sh_h1T[i] = 0.f; }
    for (int i = tid; i < MROWS * NU; i += NTHR) { sh_c0[i] = 0.f; sh_c1[i] = 0.f; }
    // (first gemm iteration's __syncthreads orders the zero-init)

    for (int n = 0; n < NNOTES; n++) {
        // ---- stage x TRANSPOSED: xT[c][r]; coalesced global reads, scattered STS ----
        for (int idx = tid; idx < MROWS * NF; idx += NTHR) {
            int r = idx >> 8;          // NF = 256
            int c = idx & 255;
            sh_xT[c * ASTR + r] = feats[((batch0 + r) * NNOTES + n) * NF + c];
        }
        if (tid < MROWS * 4) {
            int r = tid >> 2, j = tid & 3;
            float v = 0.f;
            if (j < 3 && n > 0) v = cond[((batch0 + r) * NNOTES + (n - 1)) * 3 + j];
            sh_xT[(NF + j) * ASTR + r] = v;   // cols 256..258 = shifted cond, 259 = pad 0
        }
        // (gemm's first-iteration barrier orders these writes before reads)

        u64 acc[4][4];

        // ---- layer 0: gates = [x ++ h0_prev] @ W0^T + b0 ----
#pragma unroll
        for (int g = 0; g < 4; g++) {
            u64 bv = pack2(g_b0[g * 256 + ug]);
#pragma unroll
            for (int rp = 0; rp < 4; rp++) acc[rp][g] = bv;
        }
        gemm_layer(acc, sh_xT, sh_h0T, 260 / KC, g_W0, K0TOT / KC,
                   sh_w, sw_u32, tid, rg8, ug);
        cell_update(acc, sh_c0, sh_h0T, rg8, ug);

        // ---- layer 1: gates = [h0_new ++ h1_prev] @ W1^T + b1 ----
#pragma unroll
        for (int g = 0; g < 4; g++) {
            u64 bv = pack2(g_b1[g * 256 + ug]);
#pragma unroll
            for (int rp = 0; rp < 4; rp++) acc[rp][g] = bv;
        }
        gemm_layer(acc, sh_h0T, sh_h1T, 256 / KC, g_W1, K1TOT / KC,
                   sh_w, sw_u32, tid, rg8, ug);
        cell_update(acc, sh_c1, sh_h1T, rg8, ug);

        // ---- output head: out[b,n,ch] = sigmoid?(h1 . Wout[ch] + bout[ch]) ----
        if (tid < MROWS * 3) {
            int r = tid / 3, ch = tid - r * 3;
            const float* wv = Wout + ch * NU;
            float s = bout[ch];
#pragma unroll 8
            for (int u2 = 0; u2 < NU; u2++)
                s += sh_h1T[u2 * ASTR + r] * wv[u2];
            if (ch < 2) s = sigf(s);
            out[((batch0 + r) * NNOTES + n) * 3 + ch] = s;
        }
        // next staging (xT) is disjoint from h1T; gemm's first barrier gates reuse
    }
}

// ---------------- launch ----------------
extern "C" void kernel_launch(void* const* d_in, const int* in_sizes, int n_in,
                              void* d_out, int out_size)
{
    const float* feats = (const float*)d_in[0];
    const float* cond  = (const float*)d_in[1];
    const float* W_ih0 = (const float*)d_in[2];
    const float* W_hh0 = (const float*)d_in[3];
    const float* b_ih0 = (const float*)d_in[4];
    const float* b_hh0 = (const float*)d_in[5];
    const float* W_ih1 = (const float*)d_in[6];
    const float* W_hh1 = (const float*)d_in[7];
    const float* b_ih1 = (const float*)d_in[8];
    const float* b_hh1 = (const float*)d_in[9];
    const float* W_out = (const float*)d_in[10];
    const float* b_out = (const float*)d_in[11];
    float* out = (float*)d_out;

    prep_kernel<<<264, 256>>>(W_ih0, W_hh0, b_ih0, b_hh0, W_ih1, W_hh1, b_ih1, b_hh1);

    int smem_bytes = (NSTAGE * KC * NG + 260 * ASTR + 2 * NU * ASTR + 2 * MROWS * NU)
                     * (int)sizeof(float);   // 225,856 B
    cudaFuncSetAttribute(noteaxis_kernel,
                         cudaFuncAttributeMaxDynamicSharedMemorySize, smem_bytes);
    noteaxis_kernel<<<NB / MROWS, NTHR, smem_bytes>>>(feats, cond, W_out, b_out, out);
}

// round 10
// speedup vs baseline: 1.0019x; 1.0019x over previous
#include <cuda_runtime.h>

// ---------------- problem constants ----------------
#define NB      4096
#define NNOTES  48
#define NF      256
#define NU      256
#define NG      1024      // 4 * NU (i,f,g,o)
#define K0TOT   516       // padded ih0 (260, last row zero) + hh0 (256)
#define K1TOT   512       // ih1 (256) + hh1 (256)
#define KC      4         // K rows per pipeline chunk
#define NSTAGE  3
#define MROWS   32        // batch rows per CTA
#define NTHR    1024
#define ASTR    36        // transposed-A row stride (32 rows + 4 pad, mult of 4)

typedef unsigned long long u64;

// ---------------- device scratch (static, allocation-guard-safe) ----------------
__device__ __align__(16) float g_W0[K0TOT * NG];   // [k][gatecol] layer 0 (ih pad ++ hh)
__device__ __align__(16) float g_W1[K1TOT * NG];   // [k][gatecol] layer 1 (ih ++ hh)
__device__ __align__(16) float g_b0[NG];
__device__ __align__(16) float g_b1[NG];

// ---------------- helpers ----------------
__device__ __forceinline__ u64 pack2(float x) {
    u64 r;
    asm("mov.b64 %0, {%1, %1};" : "=l"(r) : "r"(__float_as_uint(x)));
    return r;
}
__device__ __forceinline__ u64 pack2f(float lo, float hi) {
    u64 r;
    asm("mov.b64 %0, {%1, %2};" : "=l"(r) : "r"(__float_as_uint(lo)), "r"(__float_as_uint(hi)));
    return r;
}
__device__ __forceinline__ void fma2(u64& acc, u64 a, u64 b) {
    asm("fma.rn.f32x2 %0, %1, %2, %0;" : "+l"(acc) : "l"(a), "l"(b));
}
__device__ __forceinline__ void unpack2(u64 v, float& lo, float& hi) {
    unsigned int a, b;
    asm("mov.b64 {%0, %1}, %2;" : "=r"(a), "=r"(b) : "l"(v));
    lo = __uint_as_float(a);
    hi = __uint_as_float(b);
}
__device__ __forceinline__ float sigf(float x) {
    return 1.0f / (1.0f + expf(-x));
}
__device__ __forceinline__ void cp16(unsigned dst, const float* src) {
    asm volatile("cp.async.ca.shared.global [%0], [%1], 16;" :: "r"(dst), "l"(src) : "memory");
}
__device__ __forceinline__ void cp_commit() {
    asm volatile("cp.async.commit_group;" ::: "memory");
}
__device__ __forceinline__ void cp_wait1() {
    asm volatile("cp.async.wait_group 1;" ::: "memory");
}

// ---------------- prep: transpose + concatenate weights, combine biases ----------------
__global__ void prep_kernel(const float* __restrict__ W_ih0, const float* __restrict__ W_hh0,
                            const float* __restrict__ b_ih0, const float* __restrict__ b_hh0,
                            const float* __restrict__ W_ih1, const float* __restrict__ W_hh1,
                            const float* __restrict__ b_ih1, const float* __restrict__ b_hh1) {
    int tid = blockIdx.x * blockDim.x + threadIdx.x;
    int stride = gridDim.x * blockDim.x;
    for (int i = tid; i < K0TOT * NG; i += stride) {
        int k = i / NG, j = i - k * NG;
        float v;
        if (k < 259)      v = W_ih0[j * 259 + k];     // original IN0 = 259
        else if (k == 259) v = 0.f;                   // pad row (x[259] = 0 too)
        else              v = W_hh0[j * 256 + (k - 260)];
        g_W0[i] = v;
    }
    for (int i = tid; i < K1TOT * NG; i += stride) {
        int k = i / NG, j = i - k * NG;
        g_W1[i] = (k < 256) ? W_ih1[j * 256 + k] : W_hh1[j * 256 + (k - 256)];
    }
    for (int i = tid; i < NG; i += stride) {
        g_b0[i] = b_ih0[i] + b_hh0[i];
        g_b1[i] = b_ih1[i] + b_hh1[i];
    }
}

// ---------------- GEMM over one layer (concatenated ih++hh K range) ----------------
// Thread (rg, ug): rows rg*8..rg*8+7 (lanes = row pairs), unit ug, all 4 gates.
// A operands are TRANSPOSED in smem: A[k][row], row stride ASTR.
// W staged via 3-stage cp.async pipeline, KC k-rows per chunk.
__device__ __forceinline__ void gemm_layer(
    u64 (&acc)[4][4],
    const float* A0, const float* A1, int swChunk,   // A source switches at chunk swChunk
    const float* __restrict__ Wg, int nchunks,
    const float* sh_w, unsigned sw_u32, int tid, int rg8, int ug)
{
    // prologue: stage chunks 0 and 1
#pragma unroll
    for (int p = 0; p < 2; p++) {
        cp16(sw_u32 + (unsigned)(p * (KC * NG) + tid * 4) * 4u, Wg + p * (KC * NG) + tid * 4);
        cp_commit();
    }
    int stage = 0, stage2 = 2;   // stage of chunk ci, and of chunk ci+2
    for (int ci = 0; ci < nchunks; ci++) {
        cp_wait1();              // chunk ci (and older) arrived for THIS thread's copies
        __syncthreads();         // all threads' copies of chunk ci visible; stage2 free
        if (ci + 2 < nchunks) {
            cp16(sw_u32 + (unsigned)(stage2 * (KC * NG) + tid * 4) * 4u,
                 Wg + (size_t)(ci + 2) * (KC * NG) + tid * 4);
        }
        cp_commit();             // always commit (empty groups keep the count consistent)

        const float* wb = sh_w + stage * (KC * NG) + ug;
        const float* ab = (ci < swChunk ? A0 + ci * (KC * ASTR)
                                        : A1 + (ci - swChunk) * (KC * ASTR)) + rg8;
#pragma unroll
        for (int kk = 0; kk < KC; kk++) {
            float4 a03 = *(const float4*)(ab + kk * ASTR);       // rows rg8..rg8+3 (broadcast)
            float4 a47 = *(const float4*)(ab + kk * ASTR + 4);   // rows rg8+4..rg8+7
            u64 ap0 = pack2f(a03.x, a03.y);
            u64 ap1 = pack2f(a03.z, a03.w);
            u64 ap2 = pack2f(a47.x, a47.y);
            u64 ap3 = pack2f(a47.z, a47.w);
            const float* wr = wb + kk * NG;
            u64 wi = pack2(wr[0]);
            u64 wf = pack2(wr[256]);
            u64 wg = pack2(wr[512]);
            u64 wo = pack2(wr[768]);
            fma2(acc[0][0], ap0, wi); fma2(acc[1][0], ap1, wi);
            fma2(acc[2][0], ap2, wi); fma2(acc[3][0], ap3, wi);
            fma2(acc[0][1], ap0, wf); fma2(acc[1][1], ap1, wf);
            fma2(acc[2][1], ap2, wf); fma2(acc[3][1], ap3, wf);
            fma2(acc[0][2], ap0, wg); fma2(acc[1][2], ap1, wg);
            fma2(acc[2][2], ap2, wg); fma2(acc[3][2], ap3, wg);
            fma2(acc[0][3], ap0, wo); fma2(acc[1][3], ap1, wo);
            fma2(acc[2][3], ap2, wo); fma2(acc[3][3], ap3, wo);
        }
        stage = stage + 1;  if (stage == NSTAGE)  stage = 0;
        stage2 = stage2 + 1; if (stage2 == NSTAGE) stage2 = 0;
    }
}

// ---------------- LSTM cell elementwise ----------------
// Thread owns rows rg8..rg8+7 (as 4 lane-pairs) and unit ug; c is thread-exclusive.
// Writes new h into TRANSPOSED layout hT[unit][row].
__device__ __forceinline__ void cell_update(
    u64 (&acc)[4][4], float* c_state, float* hT, int rg8, int ug)
{
    float hn[8];
#pragma unroll
    for (int rp = 0; rp < 4; rp++) {
        float i0, i1, f0, f1, g0, g1, o0, o1;
        unpack2(acc[rp][0], i0, i1);
        unpack2(acc[rp][1], f0, f1);
        unpack2(acc[rp][2], g0, g1);
        unpack2(acc[rp][3], o0, o1);
        int r0 = rg8 + 2 * rp;
        float c0 = c_state[r0 * NU + ug];
        float c1 = c_state[(r0 + 1) * NU + ug];
        float cn0 = sigf(f0) * c0 + sigf(i0) * tanhf(g0);
        float cn1 = sigf(f1) * c1 + sigf(i1) * tanhf(g1);
        c_state[r0 * NU + ug]       = cn0;
        c_state[(r0 + 1) * NU + ug] = cn1;
        hn[2 * rp]     = sigf(o0) * tanhf(cn0);
        hn[2 * rp + 1] = sigf(o1) * tanhf(cn1);
    }
    __syncthreads();   // all GEMM readers of old hT are done
    float4* d = (float4*)(hT + ug * ASTR + rg8);
    d[0] = make_float4(hn[0], hn[1], hn[2], hn[3]);
    d[1] = make_float4(hn[4], hn[5], hn[6], hn[7]);
    __syncthreads();   // new hT visible (output head / next GEMM)
}

// ---------------- main persistent kernel ----------------
__global__ void __launch_bounds__(NTHR, 1)
noteaxis_kernel(const float* __restrict__ feats,
                const float* __restrict__ cond,
                const float* __restrict__ Wout,
                const float* __restrict__ bout,
                float* __restrict__ out)
{
    extern __shared__ float smem[];
    float* sh_w   = smem;                          // 3*4*1024 = 12288 floats
    float* sh_xT  = sh_w + NSTAGE * KC * NG;       // 260*36   = 9360
    float* sh_h0T = sh_xT + 260 * ASTR;            // 256*36   = 9216
    float* sh_h1T = sh_h0T + NU * ASTR;            // 9216
    float* sh_c0  = sh_h1T + NU * ASTR;            // 32*256   = 8192
    float* sh_c1  = sh_c0 + MROWS * NU;            // 8192
    unsigned sw_u32 = (unsigned)__cvta_generic_to_shared(sh_w);

    int tid = threadIdx.x;
    int rg  = tid >> 8;        // 0..3, warp-uniform
    int ug  = tid & 255;       // unit index
    int rg8 = rg * 8;
    size_t batch0 = (size_t)blockIdx.x * MROWS;

    for (int i = tid; i < NU * ASTR; i += NTHR) { sh_h0T[i] = 0.f; sh_h1T[i] = 0.f; }
    for (int i = tid; i < MROWS * NU; i += NTHR) { sh_c0[i] = 0.f; sh_c1[i] = 0.f; }
    // (first gemm iteration's __syncthreads orders the zero-init)

    for (int n = 0; n < NNOTES; n++) {
        // ---- stage x TRANSPOSED: xT[c][r]; coalesced global reads, scattered STS ----
        for (int idx = tid; idx < MROWS * NF; idx += NTHR) {
            int r = idx >> 8;          // NF = 256
            int c = idx & 255;
            sh_xT[c * ASTR + r] = feats[((batch0 + r) * NNOTES + n) * NF + c];
        }
        if (tid < MROWS * 4) {
            int r = tid >> 2, j = tid & 3;
            float v = 0.f;
            if (j < 3 && n > 0) v = cond[((batch0 + r) * NNOTES + (n - 1)) * 3 + j];
            sh_xT[(NF + j) * ASTR + r] = v;   // cols 256..258 = shifted cond, 259 = pad 0
        }
        // (gemm's first-iteration barrier orders these writes before reads)

        u64 acc[4][4];

        // ---- layer 0: gates = [x ++ h0_prev] @ W0^T + b0 ----
#pragma unroll
        for (int g = 0; g < 4; g++) {
            u64 bv = pack2(g_b0[g * 256 + ug]);
#pragma unroll
            for (int rp = 0; rp < 4; rp++) acc[rp][g] = bv;
        }
        gemm_layer(acc, sh_xT, sh_h0T, 260 / KC, g_W0, K0TOT / KC,
                   sh_w, sw_u32, tid, rg8, ug);
        cell_update(acc, sh_c0, sh_h0T, rg8, ug);

        // ---- layer 1: gates = [h0_new ++ h1_prev] @ W1^T + b1 ----
#pragma unroll
        for (int g = 0; g < 4; g++) {
            u64 bv = pack2(g_b1[g * 256 + ug]);
#pragma unroll
            for (int rp = 0; rp < 4; rp++) acc[rp][g] = bv;
        }
        gemm_layer(acc, sh_h0T, sh_h1T, 256 / KC, g_W1, K1TOT / KC,
                   sh_w, sw_u32, tid, rg8, ug);
        cell_update(acc, sh_c1, sh_h1T, rg8, ug);

        // ---- output head: out[b,n,ch] = sigmoid?(h1 . Wout[ch] + bout[ch]) ----
        if (tid < MROWS * 3) {
            int r = tid / 3, ch = tid - r * 3;
            const float* wv = Wout + ch * NU;
            float s = bout[ch];
#pragma unroll 8
            for (int u2 = 0; u2 < NU; u2++)
                s += sh_h1T[u2 * ASTR + r] * wv[u2];
            if (ch < 2) s = sigf(s);
            out[((batch0 + r) * NNOTES + n) * 3 + ch] = s;
        }
        // next staging (xT) is disjoint from h1T; gemm's first barrier gates reuse
    }
}

// ---------------- launch ----------------
extern "C" void kernel_launch(void* const* d_in, const int* in_sizes, int n_in,
                              void* d_out, int out_size)
{
    const float* feats = (const float*)d_in[0];
    const float* cond  = (const float*)d_in[1];
    const float* W_ih0 = (const float*)d_in[2];
    const float* W_hh0 = (const float*)d_in[3];
    const float* b_ih0 = (const float*)d_in[4];
    const float* b_hh0 = (const float*)d_in[5];
    const float* W_ih1 = (const float*)d_in[6];
    const float* W_hh1 = (const float*)d_in[7];
    const float* b_ih1 = (const float*)d_in[8];
    const float* b_hh1 = (const float*)d_in[9];
    const float* W_out = (const float*)d_in[10];
    const float* b_out = (const float*)d_in[11];
    float* out = (float*)d_out;

    prep_kernel<<<264, 256>>>(W_ih0, W_hh0, b_ih0, b_hh0, W_ih1, W_hh1, b_ih1, b_hh1);

    int smem_bytes = (NSTAGE * KC * NG + 260 * ASTR + 2 * NU * ASTR + 2 * MROWS * NU)
                     * (int)sizeof(float);   // 225,856 B
    cudaFuncSetAttribute(noteaxis_kernel,
                         cudaFuncAttributeMaxDynamicSharedMemorySize, smem_bytes);
    noteaxis_kernel<<<NB / MROWS, NTHR, smem_bytes>>>(feats, cond, W_out, b_out, out);
}